// round 16
// baseline (speedup 1.0000x reference)
#include <cuda_runtime.h>
#include <cuda_bf16.h>
#include <mma.h>
#include <cstdint>

using namespace nvcuda;

#define GEXP 16
#define DDIM 512
#define BMAX 4096
#define TILEM 64
#define MAXTILES (BMAX / TILEM + GEXP)
#define KCH 16
#define NCHUNK (DDIM / KCH)            // 32
// stage layout (bytes): A1 [64][32]@0, A2 @2048, B1 [128][32]@4096, B2 @8192
#define OFF_A2 2048
#define OFF_B1 4096
#define OFF_B2 8192
#define STAGE_BYTES 12288
#define NSTAGE 5
#define SMEM_TOTAL (NSTAGE * STAGE_BYTES)   // 61440; x3 CTAs = 184320 <= 228KB
#define LDS_F32 132                          // staging 64*132*4 = 33792 fits

// ---------------- device scratch (static; no allocations allowed) ----------
__device__ int g_offsets[GEXP + 1];
__device__ int g_perm[BMAX];
__device__ int g_tile_expert[MAXTILES];
__device__ int g_tile_row[MAXTILES];
__device__ int g_num_tiles;

// int8 two-level weights, TRANSPOSED: [mat][g][h][d] (d contiguous)
__device__ signed char g_Wq1[4][GEXP * DDIM * DDIM];
__device__ signed char g_Wq2[4][GEXP * DDIM * DDIM];
__device__ float       g_sW[4][GEXP * DDIM];      // per (mat, g, h)
// features int8 two-level (original token order) + per-row scale
__device__ signed char g_Aq1[BMAX * DDIM];
__device__ signed char g_Aq2[BMAX * DDIM];
__device__ float       g_sA[BMAX];
// layer-0 hidden int8 two-level, permuted order, FIXED scale 1/127, [branch]
__device__ signed char g_Hq1[2][BMAX * DDIM];
__device__ signed char g_Hq2[2][BMAX * DDIM];

// ---------------- helpers ---------------------------------------------------
__device__ __forceinline__ uint32_t smem_u32(const void* p) {
    uint32_t a;
    asm("{ .reg .u64 t; cvta.to.shared.u64 t, %1; cvt.u32.u64 %0, t; }" : "=r"(a) : "l"(p));
    return a;
}

__device__ __forceinline__ void cp16(uint32_t dst, const void* src) {
    size_t gsrc = (size_t)__cvta_generic_to_global(src);
    asm volatile("cp.async.cg.shared.global [%0], [%1], 16;" :: "r"(dst), "l"(gsrc) : "memory");
}

__device__ __forceinline__ signed char clamp127(float v) {
    v = fminf(fmaxf(v, -127.f), 127.f);
    return (signed char)(int)v;
}

// ---------------------------------------------------------------------------
// Setup: dtype-detect goal (parallel), histogram, offsets, perm, tile list.
// ---------------------------------------------------------------------------
__global__ void setup_kernel(const void* __restrict__ goal_raw, int B)
{
    __shared__ int s_cnt[GEXP];
    __shared__ int s_off[GEXP + 1];
    __shared__ int s_fill[GEXP];
    __shared__ int s_ok;

    int t = threadIdx.x;
    if (t < GEXP) { s_cnt[t] = 0; s_fill[t] = 0; }
    if (t == 0) s_ok = 1;
    __syncthreads();
    if (t < 32) {
        long long v = ((const long long*)goal_raw)[t];
        if (v < 0 || v >= GEXP) atomicExch(&s_ok, 0);
    }
    __syncthreads();
    const int is64 = s_ok;

    for (int i = t; i < B; i += blockDim.x) {
        int g = is64 ? (int)((const long long*)goal_raw)[i]
                     : ((const int*)goal_raw)[i];
        atomicAdd(&s_cnt[g], 1);
    }
    __syncthreads();

    if (t == 0) {
        int acc = 0, nt = 0;
        for (int g = 0; g < GEXP; g++) {
            s_off[g] = acc;
            for (int r = 0; r < s_cnt[g]; r += TILEM) {
                g_tile_expert[nt] = g;
                g_tile_row[nt]    = acc + r;
                nt++;
            }
            acc += s_cnt[g];
        }
        s_off[GEXP] = acc;
        g_num_tiles = nt;
        for (int g = 0; g <= GEXP; g++) g_offsets[g] = s_off[g];
    }
    __syncthreads();

    for (int i = t; i < B; i += blockDim.x) {
        int g = is64 ? (int)((const long long*)goal_raw)[i]
                     : ((const int*)goal_raw)[i];
        int pos = s_off[g] + atomicAdd(&s_fill[g], 1);
        g_perm[pos] = i;
    }
}

// ---------------------------------------------------------------------------
// Features -> int8 two-level, per-row scale. One warp per row.
// ---------------------------------------------------------------------------
__global__ void convert_f_q(const float* __restrict__ X, int B)
{
    int warp = (blockIdx.x * blockDim.x + threadIdx.x) >> 5;
    int lane = threadIdx.x & 31;
    if (warp >= B) return;

    const float4* src = (const float4*)(X + (size_t)warp * DDIM) + lane * 4;
    float4 v[4];
    float mx = 1e-30f;
    #pragma unroll
    for (int i = 0; i < 4; i++) {
        v[i] = src[i];
        mx = fmaxf(mx, fmaxf(fmaxf(fabsf(v[i].x), fabsf(v[i].y)),
                             fmaxf(fabsf(v[i].z), fabsf(v[i].w))));
    }
    #pragma unroll
    for (int o = 16; o > 0; o >>= 1)
        mx = fmaxf(mx, __shfl_xor_sync(0xFFFFFFFF, mx, o));

    float sa = mx / 127.f;
    float inv = 127.f / mx;

    signed char q1[16], q2[16];
    const float* vf = (const float*)v;
    #pragma unroll
    for (int i = 0; i < 16; i++) {
        float x = vf[i];
        float a = rintf(x * inv);                 // |x|*inv <= 127
        float resid = x - a * sa;
        float b = rintf(resid * 256.f * inv);     // in [-128,128]
        q1[i] = (signed char)(int)a;
        q2[i] = clamp127(b);
    }
    *(int4*)(g_Aq1 + (size_t)warp * DDIM + lane * 16) = *(const int4*)q1;
    *(int4*)(g_Aq2 + (size_t)warp * DDIM + lane * 16) = *(const int4*)q2;
    if (lane == 0) g_sA[warp] = sa;
}

// ---------------------------------------------------------------------------
// Weight scales: per output column h, max |W[g,:,h]| / 127.
// ---------------------------------------------------------------------------
__global__ void convert_w_scale(
    const float* __restrict__ Wp0, const float* __restrict__ Wp1,
    const float* __restrict__ Wv0, const float* __restrict__ Wv1)
{
    const int h   = blockIdx.x * 128 + threadIdx.x;   // blockIdx.x < 4
    const int g   = blockIdx.y;
    const int mat = blockIdx.z;
    const float* W = (mat == 0) ? Wp0 : (mat == 1) ? Wp1 : (mat == 2) ? Wv0 : Wv1;
    const float* Wg = W + (size_t)g * DDIM * DDIM;
    float mx = 1e-30f;
    for (int d = 0; d < DDIM; d++)
        mx = fmaxf(mx, fabsf(Wg[(size_t)d * DDIM + h]));
    g_sW[mat][g * DDIM + h] = mx / 127.f;
}

// ---------------------------------------------------------------------------
// Weight quantize + transpose: W[g][d][h] fp32 -> Wq[g][h][d] int8 x2 levels.
// 64x64 tiles through smem. blockIdx.x = dblk*8 + hblk.
// ---------------------------------------------------------------------------
__global__ __launch_bounds__(256) void convert_w_q(
    const float* __restrict__ Wp0, const float* __restrict__ Wp1,
    const float* __restrict__ Wv0, const float* __restrict__ Wv1)
{
    __shared__ float tile[64][65];
    const int dblk = blockIdx.x >> 3;
    const int hblk = blockIdx.x & 7;
    const int g    = blockIdx.y;
    const int mat  = blockIdx.z;
    const float* W = (mat == 0) ? Wp0 : (mat == 1) ? Wp1 : (mat == 2) ? Wv0 : Wv1;
    const float* Wg = W + (size_t)g * DDIM * DDIM;

    const int t  = threadIdx.x;
    const int tx = t & 63;          // h within tile
    const int tg = t >> 6;          // 0..3

    #pragma unroll
    for (int i = 0; i < 16; i++) {
        int d = tg * 16 + i;
        tile[d][tx] = Wg[(size_t)(dblk * 64 + d) * DDIM + hblk * 64 + tx];
    }
    __syncthreads();

    const int hl = t >> 2;          // 0..63 (h within tile)
    const int dp = (t & 3) * 16;    // d part
    const int h  = hblk * 64 + hl;
    float sw  = g_sW[mat][g * DDIM + h];
    float inv = 1.f / sw;

    signed char q1[16], q2[16];
    #pragma unroll
    for (int i = 0; i < 16; i++) {
        float w = tile[dp + i][hl];
        float a = rintf(w * inv);
        float resid = w - a * sw;
        float b = rintf(resid * 256.f * inv);
        q1[i] = (signed char)(int)a;
        q2[i] = clamp127(b);
    }
    size_t o = ((size_t)g * DDIM + h) * DDIM + dblk * 64 + dp;
    *(int4*)(g_Wq1[mat] + o) = *(const int4*)q1;
    *(int4*)(g_Wq2[mat] + o) = *(const int4*)q2;
}

// ---------------------------------------------------------------------------
// Grouped GEMM via int8 WMMA (IMMA): CTA 64x128, 8 warps (16x64 each),
// 5-stage ring, two chunks per barrier. Two-level int8 split:
// P = q1a*q1b, C = q1a*q2b + q2a*q1b; out = sa*sw*(P + C/256).
// ---------------------------------------------------------------------------
#define LOAD_CHUNK(S)                                                          \
    do {                                                                       \
        const uint32_t _b = sbase + ((S) % NSTAGE) * STAGE_BYTES;              \
        if (t < 128 && paA) cp16(_b + dstA, paA + (S) * KCH);                  \
        cp16(_b + dstB, pbB + (S) * KCH);                                      \
    } while (0)

__global__ __launch_bounds__(256, 3)
void gemm_layer(const float* __restrict__ bias_pi, const float* __restrict__ bias_vf,
                float* __restrict__ out, int layer, int B)
{
    const int tile = blockIdx.x;
    if (tile >= g_num_tiles) return;
    const int g    = g_tile_expert[tile];
    const int row0 = g_tile_row[tile];
    int rows = g_offsets[g + 1] - row0;
    if (rows > TILEM) rows = TILEM;
    const int n0 = blockIdx.y * 128;
    const int z  = blockIdx.z;
    const int mat = z * 2 + layer;

    extern __shared__ char smem[];
    const uint32_t sbase = smem_u32(smem);
    const int t   = threadIdx.x;
    const int wid = t >> 5;

    // ---- A loader task (threads 0..127): r = t>>1, level = t&1 ----
    const signed char* paA = nullptr;
    uint32_t dstA = 0;
    int r_a = -1;
    if (t < 128) {
        r_a = t >> 1;
        const int lvl = t & 1;
        dstA = lvl * OFF_A2 + r_a * 32;
        if (r_a < rows) {
            if (layer == 0) {
                int arow = g_perm[row0 + r_a];
                paA = (lvl ? g_Aq2 : g_Aq1) + (size_t)arow * DDIM;
            } else {
                paA = (lvl ? g_Hq2[z] : g_Hq1[z]) + (size_t)(row0 + r_a) * DDIM;
            }
        }
    }
    // ---- B loader task (all 256): n = t>>1, level = t&1 ----
    {
    }
    const int nB = t >> 1;
    const int lvB = t & 1;
    const uint32_t dstB = OFF_B1 + lvB * (OFF_B2 - OFF_B1) + nB * 32;
    const signed char* pbB =
        (lvB ? g_Wq2[mat] : g_Wq1[mat]) + ((size_t)(g * DDIM + n0 + nB)) * DDIM;

    // zero invalid A slots in all stages
    if (t < 128 && r_a >= rows) {
        int4 zz = make_int4(0, 0, 0, 0);
        #pragma unroll
        for (int st = 0; st < NSTAGE; st++)
            *(int4*)(smem + st * STAGE_BYTES + dstA) = zz;
    }

    const int wm0 = (wid & 3) * 16;
    const int wn0 = (wid >> 2) * 64;

    wmma::fragment<wmma::accumulator, 16, 16, 16, int> accP[4], accC[4];
    #pragma unroll
    for (int j = 0; j < 4; j++) {
        wmma::fill_fragment(accP[j], 0);
        wmma::fill_fragment(accC[j], 0);
    }

    LOAD_CHUNK(0);
    asm volatile("cp.async.commit_group;" ::: "memory");
    LOAD_CHUNK(1);
    asm volatile("cp.async.commit_group;" ::: "memory");
    LOAD_CHUNK(2);
    asm volatile("cp.async.commit_group;" ::: "memory");

    #pragma unroll 1
    for (int p = 0; p < NCHUNK / 2; p++) {
        if (p < NCHUNK / 2 - 1)
            asm volatile("cp.async.wait_group 1;" ::: "memory");
        else
            asm volatile("cp.async.wait_group 0;" ::: "memory");
        __syncthreads();

        if (2 * p + 3 < NCHUNK) {
            LOAD_CHUNK(2 * p + 3);
            asm volatile("cp.async.commit_group;" ::: "memory");
        }
        if (2 * p + 4 < NCHUNK) {
            LOAD_CHUNK(2 * p + 4);
            asm volatile("cp.async.commit_group;" ::: "memory");
        }

        #pragma unroll
        for (int t2 = 0; t2 < 2; t2++) {
            const int ss = 2 * p + t2;
            const char* st = smem + (ss % NSTAGE) * STAGE_BYTES;
            const signed char* A1 = (const signed char*)(st);
            const signed char* A2 = (const signed char*)(st + OFF_A2);
            const signed char* B1 = (const signed char*)(st + OFF_B1);
            const signed char* B2 = (const signed char*)(st + OFF_B2);

            wmma::fragment<wmma::matrix_a, 16, 16, 16, signed char, wmma::row_major> fa1, fa2;
            wmma::load_matrix_sync(fa1, A1 + wm0 * 32, 32);
            wmma::load_matrix_sync(fa2, A2 + wm0 * 32, 32);

            #pragma unroll
            for (int j = 0; j < 4; j++) {
                wmma::fragment<wmma::matrix_b, 16, 16, 16, signed char, wmma::col_major> fb;
                wmma::load_matrix_sync(fb, B1 + (wn0 + j * 16) * 32, 32);
                wmma::mma_sync(accP[j], fa1, fb, accP[j]);
                wmma::mma_sync(accC[j], fa2, fb, accC[j]);
                wmma::load_matrix_sync(fb, B2 + (wn0 + j * 16) * 32, 32);
                wmma::mma_sync(accC[j], fa1, fb, accC[j]);
            }
        }
    }

    __syncthreads();   // compute done before staging overwrites operand smem

    // ---- combine levels and stage as f32 ----
    float* stage = (float*)smem;
    #pragma unroll
    for (int j = 0; j < 4; j++) {
        wmma::fragment<wmma::accumulator, 16, 16, 16, float> fs;
        #pragma unroll
        for (int e = 0; e < fs.num_elements; e++)
            fs.x[e] = (float)accP[j].x[e] + (float)accC[j].x[e] * (1.f / 256.f);
        wmma::store_matrix_sync(stage + wm0 * LDS_F32 + wn0 + j * 16,
                                fs, LDS_F32, wmma::mem_row_major);
    }
    __syncthreads();

    // ---- epilogue: scale + bias + tanh ----
    const int m     = t >> 2;           // 0..63
    const int cbase = (t & 3) * 32;     // 0,32,64,96
    if (m < rows) {
        const int prow = row0 + m;
        const float sa = (layer == 0) ? g_sA[g_perm[prow]] : (1.f / 127.f);
        const float* bias = ((z == 0) ? bias_pi : bias_vf) + g * DDIM + n0 + cbase;
        const float* swp  = g_sW[mat] + g * DDIM + n0 + cbase;
        const float* srow = stage + m * LDS_F32 + cbase;

        if (layer == 0) {
            signed char q1[32], q2[32];
            #pragma unroll
            for (int c = 0; c < 32; c++) {
                float v = tanhf(sa * __ldg(swp + c) * srow[c] + __ldg(bias + c));
                float a = rintf(v * 127.f);
                float resid = v - a * (1.f / 127.f);
                float b = rintf(resid * 127.f * 256.f);
                q1[c] = (signed char)(int)a;
                q2[c] = clamp127(b);
            }
            size_t o = (size_t)prow * DDIM + n0 + cbase;
            *(int4*)(g_Hq1[z] + o)      = *(const int4*)q1;
            *(int4*)(g_Hq1[z] + o + 16) = *(const int4*)(q1 + 16);
            *(int4*)(g_Hq2[z] + o)      = *(const int4*)q2;
            *(int4*)(g_Hq2[z] + o + 16) = *(const int4*)(q2 + 16);
        } else {
            int orow = g_perm[prow];
            float* OF = out + ((size_t)z * B + orow) * DDIM + n0 + cbase;
            #pragma unroll
            for (int c = 0; c < 32; c += 4) {
                float4 o;
                o.x = tanhf(sa * __ldg(swp + c)     * srow[c]     + __ldg(bias + c));
                o.y = tanhf(sa * __ldg(swp + c + 1) * srow[c + 1] + __ldg(bias + c + 1));
                o.z = tanhf(sa * __ldg(swp + c + 2) * srow[c + 2] + __ldg(bias + c + 2));
                o.w = tanhf(sa * __ldg(swp + c + 3) * srow[c + 3] + __ldg(bias + c + 3));
                *(float4*)(OF + c) = o;
            }
        }
    }
}

// ---------------------------------------------------------------------------
extern "C" void kernel_launch(void* const* d_in, const int* in_sizes, int n_in,
                              void* d_out, int out_size)
{
    const float* features = (const float*)d_in[0];
    const float* Wp0 = (const float*)d_in[1];
    const float* bp0 = (const float*)d_in[2];
    const float* Wp1 = (const float*)d_in[3];
    const float* bp1 = (const float*)d_in[4];
    const float* Wv0 = (const float*)d_in[5];
    const float* bv0 = (const float*)d_in[6];
    const float* Wv1 = (const float*)d_in[7];
    const float* bv1 = (const float*)d_in[8];
    const void*  goal = d_in[9];

    int B = in_sizes[0] / DDIM;
    if (B > BMAX) B = BMAX;

    cudaFuncSetAttribute(gemm_layer, cudaFuncAttributeMaxDynamicSharedMemorySize, SMEM_TOTAL);

    setup_kernel<<<1, 1024>>>(goal, B);
    convert_f_q<<<(B + 7) / 8, 256>>>(features, B);
    convert_w_scale<<<dim3(4, GEXP, 4), 128>>>(Wp0, Wp1, Wv0, Wv1);
    convert_w_q<<<dim3(64, GEXP, 4), 256>>>(Wp0, Wp1, Wv0, Wv1);

    dim3 gg(B / TILEM + GEXP, 4, 2);
    gemm_layer<<<gg, 256, SMEM_TOTAL>>>(bp0, bv0, nullptr, 0, B);
    gemm_layer<<<gg, 256, SMEM_TOTAL>>>(bp1, bv1, (float*)d_out, 1, B);
}